// round 5
// baseline (speedup 1.0000x reference)
#include <cuda_runtime.h>
#include <cuda_fp16.h>
#include <cstdint>

#define BATCH   512
#define MEM     256            // K dimension
#define FEAT    512
#define NCOL    131072         // 64*2048
#define TOPK    16

#define NCHUNK  64             // N columns per gemm CTA
#define GRID    (NCOL / NCHUNK)      // 2048
#define GT      512            // gemm threads (16 warps)

#define APAD    72             // halfs per A row in smem (64 + 8 pad)
#define BPAD    264            // halfs per B^T row in smem (256 + 8 pad)
#define A_BUF   (512 * APAD)   // halfs per A k-chunk buffer
#define DYN_SMEM ((2 * A_BUF + NCHUNK * BPAD) * 2)   // 181248 bytes

// Dense fp16 weight matrix W[512][256], linear row-major. Built by kernel 1.
__device__ __align__(16) __half g_W[BATCH * MEM];

// ---------------------------------------------------------------------------
// Kernel 1: cosine sim + top-16 + clamp + renormalize -> dense fp16 W.
// 128 blocks x 256 threads; each block handles 4 batches.
// ---------------------------------------------------------------------------
__global__ void __launch_bounds__(256)
topk_kernel(const float* __restrict__ features, const float* __restrict__ keys) {
    __shared__ float f_s[4 * FEAT];
    __shared__ float fn_s[4];
    __shared__ float sim_s[4 * 264];
    __shared__ float topv_s[4][TOPK];
    __shared__ int   topi_s[4][TOPK];
    __shared__ float w_dense[4][MEM];

    const int t    = threadIdx.x;
    const int warp = t >> 5;
    const int lane = t & 31;
    const int base = blockIdx.x * 4;

    float4* f4s = reinterpret_cast<float4*>(f_s);
    const float4* fg = reinterpret_cast<const float4*>(features) + (size_t)base * (FEAT / 4);
    for (int i = t; i < 4 * FEAT / 4; i += 256) f4s[i] = fg[i];
    __syncthreads();

    if (warp < 4) {
        float s = 0.f;
#pragma unroll
        for (int m = 0; m < FEAT / 32; m++) {
            float v = f_s[warp * FEAT + lane + m * 32];
            s += v * v;
        }
#pragma unroll
        for (int off = 16; off; off >>= 1) s += __shfl_down_sync(0xffffffffu, s, off);
        if (lane == 0) fn_s[warp] = fmaxf(sqrtf(s), 1e-8f);
    }
    __syncthreads();

    const float4* krow = reinterpret_cast<const float4*>(keys) + (size_t)t * (FEAT / 4);
    float acc[4] = {0.f, 0.f, 0.f, 0.f};
    float kn = 0.f;
#pragma unroll 4
    for (int d = 0; d < FEAT / 4; d++) {
        float4 kv = krow[d];
        kn += kv.x * kv.x + kv.y * kv.y + kv.z * kv.z + kv.w * kv.w;
#pragma unroll
        for (int b = 0; b < 4; b++) {
            float4 fv = f4s[b * (FEAT / 4) + d];
            acc[b] += kv.x * fv.x + kv.y * fv.y + kv.z * fv.z + kv.w * fv.w;
        }
    }
    const float rkn = fmaxf(sqrtf(kn), 1e-8f);
#pragma unroll
    for (int b = 0; b < 4; b++)
        sim_s[b * 264 + t] = acc[b] / (fn_s[b] * rkn);

#pragma unroll
    for (int r = 0; r < 4; r++) w_dense[r][t] = 0.f;
    __syncthreads();

    if (warp < 4) {
        float v[8];
#pragma unroll
        for (int m = 0; m < 8; m++) v[m] = sim_s[warp * 264 + lane * 8 + m];

        for (int k = 0; k < TOPK; k++) {
            float best = v[0];
            int bm = 0;
#pragma unroll
            for (int m = 1; m < 8; m++)
                if (v[m] > best) { best = v[m]; bm = m; }
            int gi = lane * 8 + bm;
#pragma unroll
            for (int off = 16; off; off >>= 1) {
                float ov = __shfl_down_sync(0xffffffffu, best, off);
                int   oi = __shfl_down_sync(0xffffffffu, gi,   off);
                if (ov > best || (ov == best && oi < gi)) { best = ov; gi = oi; }
            }
            best = __shfl_sync(0xffffffffu, best, 0);
            gi   = __shfl_sync(0xffffffffu, gi,   0);
            if (lane == (gi >> 3)) {
                int li = gi & 7;
#pragma unroll
                for (int m = 0; m < 8; m++)
                    if (m == li) v[m] = -3.0e38f;
            }
            if (lane == 0) { topv_s[warp][k] = best; topi_s[warp][k] = gi; }
        }
        __syncwarp();

        float tv = (lane < TOPK) ? fmaxf(topv_s[warp][lane], 0.f) : 0.f;
        float s = tv;
#pragma unroll
        for (int off = 16; off; off >>= 1) s += __shfl_down_sync(0xffffffffu, s, off);
        s = __shfl_sync(0xffffffffu, s, 0);
        const float inv = 1.0f / s;
        if (lane < TOPK)
            w_dense[warp][topi_s[warp][lane]] = tv * inv;
    }
    __syncthreads();

    // emit linear fp16 W rows
#pragma unroll
    for (int r = 0; r < 4; r++)
        g_W[(base + r) * MEM + t] = __float2half_rn(w_dense[r][t]);
}

// ---------------------------------------------------------------------------
// Kernel 2: HMMA GEMM  out[512, 64chunk] = W[512,256] @ memory[256, chunk]
// mma.sync.m16n8k16.row.col.f32.f16.f16.f32. One CTA per 64-col chunk.
// B converted fp32->fp16, transposed [n][k] in SMEM (full K, padded).
// A staged per 64-K chunk via cp.async double buffer.
// ---------------------------------------------------------------------------
__device__ __forceinline__ void mma16816(float d[4],
                                         uint32_t a0, uint32_t a1, uint32_t a2, uint32_t a3,
                                         uint32_t b0, uint32_t b1) {
    asm volatile(
        "mma.sync.aligned.m16n8k16.row.col.f32.f16.f16.f32 "
        "{%0,%1,%2,%3}, {%4,%5,%6,%7}, {%8,%9}, {%0,%1,%2,%3};"
        : "+f"(d[0]), "+f"(d[1]), "+f"(d[2]), "+f"(d[3])
        : "r"(a0), "r"(a1), "r"(a2), "r"(a3), "r"(b0), "r"(b1));
}

__global__ void __launch_bounds__(GT, 1)
gemm_kernel(const float* __restrict__ memory, float* __restrict__ out) {
    extern __shared__ __half sm[];
    __half* As = sm;                 // [2][512][APAD]
    __half* Bs = sm + 2 * A_BUF;     // [64][BPAD]

    const int tid  = threadIdx.x;
    const int warp = tid >> 5;
    const int lane = tid & 31;
    const int g    = lane >> 2;      // group id (row within frag)
    const int tg   = lane & 3;       // thread-in-group (col pairs)
    const int chunk = blockIdx.x;

    const int mw = (warp >> 1) * 64; // warp M base (8 M-stripes)
    const int nw = (warp & 1) * 32;  // warp N base (2 N-stripes)

    // ---- stage B: fp32 gmem -> fp16 transposed smem [n][k] ----
    {
        const float4* src = reinterpret_cast<const float4*>(memory) + chunk * (NCHUNK / 4);
        for (int i = tid; i < MEM * (NCHUNK / 4); i += GT) {
            int k = i >> 4;          // 16 float4 per k-row
            int q = i & 15;
            float4 v = src[(size_t)k * (NCOL / 4) + q];
            int n = q * 4;
            Bs[(n + 0) * BPAD + k] = __float2half_rn(v.x);
            Bs[(n + 1) * BPAD + k] = __float2half_rn(v.y);
            Bs[(n + 2) * BPAD + k] = __float2half_rn(v.z);
            Bs[(n + 3) * BPAD + k] = __float2half_rn(v.w);
        }
    }

    // ---- async A-chunk stage: 512 rows x 64 halfs (16B granules) ----
    auto stage_A = [&](int kc, int buf) {
        const __half* src = g_W + kc * 64;
        __half* dst = As + buf * A_BUF;
#pragma unroll
        for (int j = 0; j < 8; j++) {
            int i = tid + j * GT;    // 4096 granules total
            int m = i >> 3, seg = i & 7;
            uint32_t sa = (uint32_t)__cvta_generic_to_shared(dst + m * APAD + seg * 8);
            const __half* gp = src + m * MEM + seg * 8;
            asm volatile("cp.async.cg.shared.global [%0], [%1], 16;" :: "r"(sa), "l"(gp) : "memory");
        }
    };

    stage_A(0, 0);
    asm volatile("cp.async.commit_group;" ::: "memory");
    asm volatile("cp.async.wait_group 0;" ::: "memory");
    __syncthreads();

    float d[4][4][4];
#pragma unroll
    for (int mi = 0; mi < 4; mi++)
#pragma unroll
        for (int ni = 0; ni < 4; ni++)
#pragma unroll
            for (int r = 0; r < 4; r++) d[mi][ni][r] = 0.f;

    // ---- K loop: 4 chunks of 64, double-buffered ----
#pragma unroll
    for (int kc = 0; kc < 4; kc++) {
        if (kc < 3) {
            stage_A(kc + 1, (kc + 1) & 1);
            asm volatile("cp.async.commit_group;" ::: "memory");
        }
        const __half* A = As + (kc & 1) * A_BUF;

#pragma unroll
        for (int ks = 0; ks < 4; ks++) {
            const int kb = ks * 16;
            const int kg = kc * 64 + kb + tg * 2;   // global k for B frags

            uint32_t bf[4][2];
#pragma unroll
            for (int ni = 0; ni < 4; ni++) {
                const __half* bp = Bs + (nw + ni * 8 + g) * BPAD + kg;
                bf[ni][0] = *reinterpret_cast<const uint32_t*>(bp);
                bf[ni][1] = *reinterpret_cast<const uint32_t*>(bp + 8);
            }
#pragma unroll
            for (int mi = 0; mi < 4; mi++) {
                const __half* ap = A + (mw + mi * 16 + g) * APAD + kb + tg * 2;
                uint32_t a0 = *reinterpret_cast<const uint32_t*>(ap);
                uint32_t a1 = *reinterpret_cast<const uint32_t*>(ap + 8 * APAD);
                uint32_t a2 = *reinterpret_cast<const uint32_t*>(ap + 8);
                uint32_t a3 = *reinterpret_cast<const uint32_t*>(ap + 8 * APAD + 8);
#pragma unroll
                for (int ni = 0; ni < 4; ni++)
                    mma16816(d[mi][ni], a0, a1, a2, a3, bf[ni][0], bf[ni][1]);
            }
        }

        if (kc < 3) {
            asm volatile("cp.async.wait_group 0;" ::: "memory");
            __syncthreads();
        }
    }

    // ---- epilogue: registers -> gmem (float2 per frag row) ----
    const size_t cbase = (size_t)chunk * NCHUNK;
#pragma unroll
    for (int mi = 0; mi < 4; mi++) {
        const int r0 = mw + mi * 16 + g;
#pragma unroll
        for (int ni = 0; ni < 4; ni++) {
            const size_t col = cbase + nw + ni * 8 + tg * 2;
            float2 v0 = make_float2(d[mi][ni][0], d[mi][ni][1]);
            float2 v1 = make_float2(d[mi][ni][2], d[mi][ni][3]);
            *reinterpret_cast<float2*>(out + (size_t)r0 * NCOL + col)       = v0;
            *reinterpret_cast<float2*>(out + (size_t)(r0 + 8) * NCOL + col) = v1;
        }
    }
}

// ---------------------------------------------------------------------------
extern "C" void kernel_launch(void* const* d_in, const int* in_sizes, int n_in,
                              void* d_out, int out_size) {
    const float* features = (const float*)d_in[0];
    const float* keys     = (const float*)d_in[1];
    const float* memory   = (const float*)d_in[2];
    float*       out      = (float*)d_out;

    cudaFuncSetAttribute(gemm_kernel,
                         cudaFuncAttributeMaxDynamicSharedMemorySize, DYN_SMEM);

    topk_kernel<<<BATCH / 4, 256>>>(features, keys);
    gemm_kernel<<<GRID, GT, DYN_SMEM>>>(memory, out);
}

// round 6
// speedup vs baseline: 1.2369x; 1.2369x over previous
#include <cuda_runtime.h>
#include <cuda_fp16.h>
#include <cstdint>

#define BATCH   512
#define MEM     256            // K dimension
#define FEAT    512
#define NCOL    131072         // 64*2048
#define TOPK    16

#define NCHUNK  64             // N columns per gemm CTA
#define GRID    (NCOL / NCHUNK)      // 2048
#define GT      512            // gemm threads (16 warps)

#define APAD    72             // halfs per A row in smem (64 + 8 pad)
#define BPAD    72             // halfs per B k-row in smem (64 + 8 pad)
#define A_BUF   (512 * APAD)   // halfs per A k-chunk buffer (36864)
#define B_BUF   (64 * BPAD)    // halfs per B k-chunk buffer (4608)
#define DYN_SMEM ((2 * A_BUF + 2 * B_BUF) * 2)   // 165888 bytes

// Dense fp16 weight matrix W[512][256], linear row-major. Built by kernel 1.
__device__ __align__(16) __half g_W[BATCH * MEM];

// ---------------------------------------------------------------------------
// Kernel 1: cosine sim + top-16 + clamp + renormalize -> dense fp16 W.
// 128 blocks x 256 threads; each block handles 4 batches.  (unchanged)
// ---------------------------------------------------------------------------
__global__ void __launch_bounds__(256)
topk_kernel(const float* __restrict__ features, const float* __restrict__ keys) {
    __shared__ float f_s[4 * FEAT];
    __shared__ float fn_s[4];
    __shared__ float sim_s[4 * 264];
    __shared__ float topv_s[4][TOPK];
    __shared__ int   topi_s[4][TOPK];
    __shared__ float w_dense[4][MEM];

    const int t    = threadIdx.x;
    const int warp = t >> 5;
    const int lane = t & 31;
    const int base = blockIdx.x * 4;

    float4* f4s = reinterpret_cast<float4*>(f_s);
    const float4* fg = reinterpret_cast<const float4*>(features) + (size_t)base * (FEAT / 4);
    for (int i = t; i < 4 * FEAT / 4; i += 256) f4s[i] = fg[i];
    __syncthreads();

    if (warp < 4) {
        float s = 0.f;
#pragma unroll
        for (int m = 0; m < FEAT / 32; m++) {
            float v = f_s[warp * FEAT + lane + m * 32];
            s += v * v;
        }
#pragma unroll
        for (int off = 16; off; off >>= 1) s += __shfl_down_sync(0xffffffffu, s, off);
        if (lane == 0) fn_s[warp] = fmaxf(sqrtf(s), 1e-8f);
    }
    __syncthreads();

    const float4* krow = reinterpret_cast<const float4*>(keys) + (size_t)t * (FEAT / 4);
    float acc[4] = {0.f, 0.f, 0.f, 0.f};
    float kn = 0.f;
#pragma unroll 4
    for (int d = 0; d < FEAT / 4; d++) {
        float4 kv = krow[d];
        kn += kv.x * kv.x + kv.y * kv.y + kv.z * kv.z + kv.w * kv.w;
#pragma unroll
        for (int b = 0; b < 4; b++) {
            float4 fv = f4s[b * (FEAT / 4) + d];
            acc[b] += kv.x * fv.x + kv.y * fv.y + kv.z * fv.z + kv.w * fv.w;
        }
    }
    const float rkn = fmaxf(sqrtf(kn), 1e-8f);
#pragma unroll
    for (int b = 0; b < 4; b++)
        sim_s[b * 264 + t] = acc[b] / (fn_s[b] * rkn);

#pragma unroll
    for (int r = 0; r < 4; r++) w_dense[r][t] = 0.f;
    __syncthreads();

    if (warp < 4) {
        float v[8];
#pragma unroll
        for (int m = 0; m < 8; m++) v[m] = sim_s[warp * 264 + lane * 8 + m];

        for (int k = 0; k < TOPK; k++) {
            float best = v[0];
            int bm = 0;
#pragma unroll
            for (int m = 1; m < 8; m++)
                if (v[m] > best) { best = v[m]; bm = m; }
            int gi = lane * 8 + bm;
#pragma unroll
            for (int off = 16; off; off >>= 1) {
                float ov = __shfl_down_sync(0xffffffffu, best, off);
                int   oi = __shfl_down_sync(0xffffffffu, gi,   off);
                if (ov > best || (ov == best && oi < gi)) { best = ov; gi = oi; }
            }
            best = __shfl_sync(0xffffffffu, best, 0);
            gi   = __shfl_sync(0xffffffffu, gi,   0);
            if (lane == (gi >> 3)) {
                int li = gi & 7;
#pragma unroll
                for (int m = 0; m < 8; m++)
                    if (m == li) v[m] = -3.0e38f;
            }
            if (lane == 0) { topv_s[warp][k] = best; topi_s[warp][k] = gi; }
        }
        __syncwarp();

        float tv = (lane < TOPK) ? fmaxf(topv_s[warp][lane], 0.f) : 0.f;
        float s = tv;
#pragma unroll
        for (int off = 16; off; off >>= 1) s += __shfl_down_sync(0xffffffffu, s, off);
        s = __shfl_sync(0xffffffffu, s, 0);
        const float inv = 1.0f / s;
        if (lane < TOPK)
            w_dense[warp][topi_s[warp][lane]] = tv * inv;
    }
    __syncthreads();

#pragma unroll
    for (int r = 0; r < 4; r++)
        g_W[(base + r) * MEM + t] = __float2half_rn(w_dense[r][t]);
}

// ---------------------------------------------------------------------------
// Kernel 2: HMMA GEMM with ldmatrix frags + fully pipelined staging.
// out[512, 64chunk] = W[512,256] @ memory[256, chunk]
// A: fp16 [m][k] padded rows, cp.async double buffer per 64-K chunk.
// B: fp16 [k][n] padded rows (same orientation as gmem; no transpose),
//    LDG fp32 one chunk ahead -> regs -> cvt -> STS, double buffered.
// Frags: ldmatrix.x4 (A), ldmatrix.x4.trans (B).
// ---------------------------------------------------------------------------
__device__ __forceinline__ void mma16816(float d[4],
                                         uint32_t a0, uint32_t a1, uint32_t a2, uint32_t a3,
                                         uint32_t b0, uint32_t b1) {
    asm volatile(
        "mma.sync.aligned.m16n8k16.row.col.f32.f16.f16.f32 "
        "{%0,%1,%2,%3}, {%4,%5,%6,%7}, {%8,%9}, {%0,%1,%2,%3};"
        : "+f"(d[0]), "+f"(d[1]), "+f"(d[2]), "+f"(d[3])
        : "r"(a0), "r"(a1), "r"(a2), "r"(a3), "r"(b0), "r"(b1));
}
__device__ __forceinline__ void ldsm_x4(uint32_t r[4], uint32_t sa) {
    asm volatile("ldmatrix.sync.aligned.m8n8.x4.shared.b16 {%0,%1,%2,%3}, [%4];"
        : "=r"(r[0]), "=r"(r[1]), "=r"(r[2]), "=r"(r[3]) : "r"(sa));
}
__device__ __forceinline__ void ldsm_x4_t(uint32_t r[4], uint32_t sa) {
    asm volatile("ldmatrix.sync.aligned.m8n8.x4.trans.shared.b16 {%0,%1,%2,%3}, [%4];"
        : "=r"(r[0]), "=r"(r[1]), "=r"(r[2]), "=r"(r[3]) : "r"(sa));
}

__global__ void __launch_bounds__(GT, 1)
gemm_kernel(const float* __restrict__ memory, float* __restrict__ out) {
    extern __shared__ __half sm[];
    __half* As = sm;                    // [2][512][APAD]
    __half* Bs = sm + 2 * A_BUF;        // [2][64][BPAD]

    const int tid  = threadIdx.x;
    const int warp = tid >> 5;
    const int lane = tid & 31;
    const int g    = lane >> 2;
    const int tg   = lane & 3;
    const int chunk = blockIdx.x;

    const int mw = (warp >> 1) * 64;    // warp M base
    const int nw = (warp & 1) * 32;     // warp N base

    // lane-invariant ldmatrix offsets (in halfs)
    const uint32_t a_lane = (uint32_t)((mw + (lane & 15)) * APAD + ((lane >> 4) << 3));
    const int bgrp = lane >> 3;
    const uint32_t b_lane = (uint32_t)(((bgrp & 1) * 8 + (lane & 7)) * BPAD
                                       + nw + (bgrp >> 1) * 8);

    const uint32_t As_base = (uint32_t)__cvta_generic_to_shared(As);
    const uint32_t Bs_base = (uint32_t)__cvta_generic_to_shared(Bs);

    // ---- B LDG helper: chunk kc -> 2 float4 regs per thread ----
    const float4* msrc = reinterpret_cast<const float4*>(memory) + chunk * (NCHUNK / 4);
    const int bk0 = tid >> 4,        bq0 = tid & 15;         // i = tid
    const int bk1 = (tid + 512) >> 4, bq1 = (tid + 512) & 15; // i = tid+512
    float4 br0, br1;

    auto ldg_B = [&](int kc) {
        br0 = msrc[(size_t)(kc * 64 + bk0) * (NCOL / 4) + bq0];
        br1 = msrc[(size_t)(kc * 64 + bk1) * (NCOL / 4) + bq1];
    };
    auto sts_B = [&](int buf) {
        __half2 h00 = __floats2half2_rn(br0.x, br0.y);
        __half2 h01 = __floats2half2_rn(br0.z, br0.w);
        __half2 h10 = __floats2half2_rn(br1.x, br1.y);
        __half2 h11 = __floats2half2_rn(br1.z, br1.w);
        uint2* d0 = reinterpret_cast<uint2*>(Bs + buf * B_BUF + bk0 * BPAD + bq0 * 4);
        uint2* d1 = reinterpret_cast<uint2*>(Bs + buf * B_BUF + bk1 * BPAD + bq1 * 4);
        *d0 = make_uint2(*reinterpret_cast<uint32_t*>(&h00), *reinterpret_cast<uint32_t*>(&h01));
        *d1 = make_uint2(*reinterpret_cast<uint32_t*>(&h10), *reinterpret_cast<uint32_t*>(&h11));
    };
    // ---- A stage: 512 rows x 64 halfs via cp.async 16B granules ----
    auto stage_A = [&](int kc, int buf) {
        const __half* src = g_W + kc * 64;
        __half* dst = As + buf * A_BUF;
#pragma unroll
        for (int j = 0; j < 8; j++) {
            int i = tid + j * GT;
            int m = i >> 3, seg = i & 7;
            uint32_t sa = (uint32_t)__cvta_generic_to_shared(dst + m * APAD + seg * 8);
            const __half* gp = src + m * MEM + seg * 8;
            asm volatile("cp.async.cg.shared.global [%0], [%1], 16;" :: "r"(sa), "l"(gp) : "memory");
        }
        asm volatile("cp.async.commit_group;" ::: "memory");
    };

    // ---- prologue ----
    ldg_B(0);
    stage_A(0, 0);
    sts_B(0);
    asm volatile("cp.async.wait_group 0;" ::: "memory");
    __syncthreads();

    float d[4][4][4];
#pragma unroll
    for (int mi = 0; mi < 4; mi++)
#pragma unroll
        for (int ni = 0; ni < 4; ni++)
#pragma unroll
            for (int r = 0; r < 4; r++) d[mi][ni][r] = 0.f;

    // ---- K loop: 4 chunks of 64, everything double-buffered ----
#pragma unroll
    for (int kc = 0; kc < 4; kc++) {
        if (kc < 3) {
            ldg_B(kc + 1);                 // DRAM latency hides under mma
            stage_A(kc + 1, (kc + 1) & 1);
        }
        const uint32_t a_base = As_base + ((kc & 1) * A_BUF + a_lane) * 2;
        const uint32_t b_base = Bs_base + ((kc & 1) * B_BUF + b_lane) * 2;

#pragma unroll
        for (int ks = 0; ks < 4; ks++) {
            uint32_t bf[8];
            ldsm_x4_t(bf,     b_base + ks * (16 * BPAD * 2));        // ni 0,1
            ldsm_x4_t(bf + 4, b_base + ks * (16 * BPAD * 2) + 32);   // ni 2,3
#pragma unroll
            for (int mi = 0; mi < 4; mi++) {
                uint32_t a[4];
                ldsm_x4(a, a_base + mi * (16 * APAD * 2) + ks * 32);
                mma16816(d[mi][0], a[0], a[1], a[2], a[3], bf[0], bf[1]);
                mma16816(d[mi][1], a[0], a[1], a[2], a[3], bf[2], bf[3]);
                mma16816(d[mi][2], a[0], a[1], a[2], a[3], bf[4], bf[5]);
                mma16816(d[mi][3], a[0], a[1], a[2], a[3], bf[6], bf[7]);
            }
        }

        if (kc < 3) {
            sts_B((kc + 1) & 1);
            asm volatile("cp.async.wait_group 0;" ::: "memory");
            __syncthreads();
        }
    }

    // ---- epilogue: registers -> gmem ----
    const size_t cbase = (size_t)chunk * NCHUNK;
#pragma unroll
    for (int mi = 0; mi < 4; mi++) {
        const int r0 = mw + mi * 16 + g;
#pragma unroll
        for (int ni = 0; ni < 4; ni++) {
            const size_t col = cbase + nw + ni * 8 + tg * 2;
            float2 v0 = make_float2(d[mi][ni][0], d[mi][ni][1]);
            float2 v1 = make_float2(d[mi][ni][2], d[mi][ni][3]);
            *reinterpret_cast<float2*>(out + (size_t)r0 * NCOL + col)       = v0;
            *reinterpret_cast<float2*>(out + (size_t)(r0 + 8) * NCOL + col) = v1;
        }
    }
}

// ---------------------------------------------------------------------------
extern "C" void kernel_launch(void* const* d_in, const int* in_sizes, int n_in,
                              void* d_out, int out_size) {
    const float* features = (const float*)d_in[0];
    const float* keys     = (const float*)d_in[1];
    const float* memory   = (const float*)d_in[2];
    float*       out      = (float*)d_out;

    cudaFuncSetAttribute(gemm_kernel,
                         cudaFuncAttributeMaxDynamicSharedMemorySize, DYN_SMEM);

    topk_kernel<<<BATCH / 4, 256>>>(features, keys);
    gemm_kernel<<<GRID, GT, DYN_SMEM>>>(memory, out);
}

// round 7
// speedup vs baseline: 1.2865x; 1.0401x over previous
#include <cuda_runtime.h>
#include <cuda_fp16.h>
#include <cstdint>

#define BATCH   512
#define MEM     256            // K dimension
#define FEAT    512
#define NCOL    131072         // 64*2048
#define TOPK    16

#define NCHUNK  64             // N columns per gemm CTA
#define MTILE   256            // M rows per gemm CTA
#define GT      256            // gemm threads (8 warps)

#define APAD    72             // halfs per A row in smem (64 + 8 pad)
#define BPAD    72             // halfs per B k-row in smem (64 + 8 pad)
#define A_BUF   (MTILE * APAD) // halfs per A k-chunk buffer (18432)
#define B_BUF   (64 * BPAD)    // halfs per B k-chunk buffer (4608)
#define DYN_SMEM ((2 * A_BUF + 2 * B_BUF) * 2)   // 92160 bytes -> 2 CTAs/SM

// Dense fp16 weight matrix W[512][256], linear row-major. Built by kernel 1.
__device__ __align__(16) __half g_W[BATCH * MEM];

// ---------------------------------------------------------------------------
// Kernel 1: cosine sim + top-16 + clamp + renormalize -> dense fp16 W.
// 128 blocks x 256 threads; each block handles 4 batches.  (unchanged)
// ---------------------------------------------------------------------------
__global__ void __launch_bounds__(256)
topk_kernel(const float* __restrict__ features, const float* __restrict__ keys) {
    __shared__ float f_s[4 * FEAT];
    __shared__ float fn_s[4];
    __shared__ float sim_s[4 * 264];
    __shared__ float topv_s[4][TOPK];
    __shared__ int   topi_s[4][TOPK];
    __shared__ float w_dense[4][MEM];

    const int t    = threadIdx.x;
    const int warp = t >> 5;
    const int lane = t & 31;
    const int base = blockIdx.x * 4;

    float4* f4s = reinterpret_cast<float4*>(f_s);
    const float4* fg = reinterpret_cast<const float4*>(features) + (size_t)base * (FEAT / 4);
    for (int i = t; i < 4 * FEAT / 4; i += 256) f4s[i] = fg[i];
    __syncthreads();

    if (warp < 4) {
        float s = 0.f;
#pragma unroll
        for (int m = 0; m < FEAT / 32; m++) {
            float v = f_s[warp * FEAT + lane + m * 32];
            s += v * v;
        }
#pragma unroll
        for (int off = 16; off; off >>= 1) s += __shfl_down_sync(0xffffffffu, s, off);
        if (lane == 0) fn_s[warp] = fmaxf(sqrtf(s), 1e-8f);
    }
    __syncthreads();

    const float4* krow = reinterpret_cast<const float4*>(keys) + (size_t)t * (FEAT / 4);
    float acc[4] = {0.f, 0.f, 0.f, 0.f};
    float kn = 0.f;
#pragma unroll 4
    for (int d = 0; d < FEAT / 4; d++) {
        float4 kv = krow[d];
        kn += kv.x * kv.x + kv.y * kv.y + kv.z * kv.z + kv.w * kv.w;
#pragma unroll
        for (int b = 0; b < 4; b++) {
            float4 fv = f4s[b * (FEAT / 4) + d];
            acc[b] += kv.x * fv.x + kv.y * fv.y + kv.z * fv.z + kv.w * fv.w;
        }
    }
    const float rkn = fmaxf(sqrtf(kn), 1e-8f);
#pragma unroll
    for (int b = 0; b < 4; b++)
        sim_s[b * 264 + t] = acc[b] / (fn_s[b] * rkn);

#pragma unroll
    for (int r = 0; r < 4; r++) w_dense[r][t] = 0.f;
    __syncthreads();

    if (warp < 4) {
        float v[8];
#pragma unroll
        for (int m = 0; m < 8; m++) v[m] = sim_s[warp * 264 + lane * 8 + m];

        for (int k = 0; k < TOPK; k++) {
            float best = v[0];
            int bm = 0;
#pragma unroll
            for (int m = 1; m < 8; m++)
                if (v[m] > best) { best = v[m]; bm = m; }
            int gi = lane * 8 + bm;
#pragma unroll
            for (int off = 16; off; off >>= 1) {
                float ov = __shfl_down_sync(0xffffffffu, best, off);
                int   oi = __shfl_down_sync(0xffffffffu, gi,   off);
                if (ov > best || (ov == best && oi < gi)) { best = ov; gi = oi; }
            }
            best = __shfl_sync(0xffffffffu, best, 0);
            gi   = __shfl_sync(0xffffffffu, gi,   0);
            if (lane == (gi >> 3)) {
                int li = gi & 7;
#pragma unroll
                for (int m = 0; m < 8; m++)
                    if (m == li) v[m] = -3.0e38f;
            }
            if (lane == 0) { topv_s[warp][k] = best; topi_s[warp][k] = gi; }
        }
        __syncwarp();

        float tv = (lane < TOPK) ? fmaxf(topv_s[warp][lane], 0.f) : 0.f;
        float s = tv;
#pragma unroll
        for (int off = 16; off; off >>= 1) s += __shfl_down_sync(0xffffffffu, s, off);
        s = __shfl_sync(0xffffffffu, s, 0);
        const float inv = 1.0f / s;
        if (lane < TOPK)
            w_dense[warp][topi_s[warp][lane]] = tv * inv;
    }
    __syncthreads();

#pragma unroll
    for (int r = 0; r < 4; r++)
        g_W[(base + r) * MEM + t] = __float2half_rn(w_dense[r][t]);
}

// ---------------------------------------------------------------------------
// Kernel 2: HMMA GEMM, 2 CTAs/SM for cross-CTA bubble overlap.
// CTA tile: M=256 (blockIdx.y half) x N=64 (blockIdx.x chunk), K=256.
// 8 warps, warp tile 64M x 32N. A/B double-buffered per 64-K chunk;
// B LDG issued one chunk ahead into registers.
// ---------------------------------------------------------------------------
__device__ __forceinline__ void mma16816(float d[4],
                                         uint32_t a0, uint32_t a1, uint32_t a2, uint32_t a3,
                                         uint32_t b0, uint32_t b1) {
    asm volatile(
        "mma.sync.aligned.m16n8k16.row.col.f32.f16.f16.f32 "
        "{%0,%1,%2,%3}, {%4,%5,%6,%7}, {%8,%9}, {%0,%1,%2,%3};"
        : "+f"(d[0]), "+f"(d[1]), "+f"(d[2]), "+f"(d[3])
        : "r"(a0), "r"(a1), "r"(a2), "r"(a3), "r"(b0), "r"(b1));
}
__device__ __forceinline__ void ldsm_x4(uint32_t r[4], uint32_t sa) {
    asm volatile("ldmatrix.sync.aligned.m8n8.x4.shared.b16 {%0,%1,%2,%3}, [%4];"
        : "=r"(r[0]), "=r"(r[1]), "=r"(r[2]), "=r"(r[3]) : "r"(sa));
}
__device__ __forceinline__ void ldsm_x4_t(uint32_t r[4], uint32_t sa) {
    asm volatile("ldmatrix.sync.aligned.m8n8.x4.trans.shared.b16 {%0,%1,%2,%3}, [%4];"
        : "=r"(r[0]), "=r"(r[1]), "=r"(r[2]), "=r"(r[3]) : "r"(sa));
}

__global__ void __launch_bounds__(GT, 2)
gemm_kernel(const float* __restrict__ memory, float* __restrict__ out) {
    extern __shared__ __half sm[];
    __half* As = sm;                    // [2][256][APAD]
    __half* Bs = sm + 2 * A_BUF;        // [2][64][BPAD]

    const int tid   = threadIdx.x;
    const int warp  = tid >> 5;
    const int lane  = tid & 31;
    const int g     = lane >> 2;
    const int tg    = lane & 3;
    const int chunk = blockIdx.x;
    const int mhalf = blockIdx.y;

    const int mw = (warp >> 1) * 64;    // warp M base within 256
    const int nw = (warp & 1) * 32;     // warp N base

    const uint32_t a_lane = (uint32_t)((mw + (lane & 15)) * APAD + ((lane >> 4) << 3));
    const int bgrp = lane >> 3;
    const uint32_t b_lane = (uint32_t)(((bgrp & 1) * 8 + (lane & 7)) * BPAD
                                       + nw + (bgrp >> 1) * 8);

    const uint32_t As_base = (uint32_t)__cvta_generic_to_shared(As);
    const uint32_t Bs_base = (uint32_t)__cvta_generic_to_shared(Bs);

    // ---- B LDG: 64k x 64n fp32 = 1024 float4; 4 per thread ----
    const float4* msrc = reinterpret_cast<const float4*>(memory) + chunk * (NCHUNK / 4);
    float4 br[4];
    auto ldg_B = [&](int kc) {
#pragma unroll
        for (int q = 0; q < 4; q++) {
            int i = tid + q * GT;
            br[q] = msrc[(size_t)(kc * 64 + (i >> 4)) * (NCOL / 4) + (i & 15)];
        }
    };
    auto sts_B = [&](int buf) {
#pragma unroll
        for (int q = 0; q < 4; q++) {
            int i = tid + q * GT;
            __half2 h0 = __floats2half2_rn(br[q].x, br[q].y);
            __half2 h1 = __floats2half2_rn(br[q].z, br[q].w);
            uint2* dp = reinterpret_cast<uint2*>(Bs + buf * B_BUF + (i >> 4) * BPAD + (i & 15) * 4);
            *dp = make_uint2(*reinterpret_cast<uint32_t*>(&h0),
                             *reinterpret_cast<uint32_t*>(&h1));
        }
    };
    // ---- A stage: 256 rows x 64 halfs via cp.async 16B granules ----
    auto stage_A = [&](int kc, int buf) {
        const __half* src = g_W + (size_t)(mhalf * MTILE) * MEM + kc * 64;
        __half* dst = As + buf * A_BUF;
#pragma unroll
        for (int j = 0; j < 8; j++) {
            int i = tid + j * GT;                 // 2048 granules total
            int m = i >> 3, seg = i & 7;
            uint32_t sa = (uint32_t)__cvta_generic_to_shared(dst + m * APAD + seg * 8);
            const __half* gp = src + m * MEM + seg * 8;
            asm volatile("cp.async.cg.shared.global [%0], [%1], 16;" :: "r"(sa), "l"(gp) : "memory");
        }
        asm volatile("cp.async.commit_group;" ::: "memory");
    };

    // ---- prologue ----
    ldg_B(0);
    stage_A(0, 0);
    sts_B(0);
    asm volatile("cp.async.wait_group 0;" ::: "memory");
    __syncthreads();

    float d[4][4][4];
#pragma unroll
    for (int mi = 0; mi < 4; mi++)
#pragma unroll
        for (int ni = 0; ni < 4; ni++)
#pragma unroll
            for (int r = 0; r < 4; r++) d[mi][ni][r] = 0.f;

    // ---- K loop: 4 chunks of 64, double-buffered ----
#pragma unroll
    for (int kc = 0; kc < 4; kc++) {
        if (kc < 3) {
            ldg_B(kc + 1);                 // DRAM latency hides under mma
            stage_A(kc + 1, (kc + 1) & 1);
        }
        const uint32_t a_base = As_base + ((kc & 1) * A_BUF + a_lane) * 2;
        const uint32_t b_base = Bs_base + ((kc & 1) * B_BUF + b_lane) * 2;

#pragma unroll
        for (int ks = 0; ks < 4; ks++) {
            uint32_t bf[8];
            ldsm_x4_t(bf,     b_base + ks * (16 * BPAD * 2));        // ni 0,1
            ldsm_x4_t(bf + 4, b_base + ks * (16 * BPAD * 2) + 32);   // ni 2,3
#pragma unroll
            for (int mi = 0; mi < 4; mi++) {
                uint32_t a[4];
                ldsm_x4(a, a_base + mi * (16 * APAD * 2) + ks * 32);
                mma16816(d[mi][0], a[0], a[1], a[2], a[3], bf[0], bf[1]);
                mma16816(d[mi][1], a[0], a[1], a[2], a[3], bf[2], bf[3]);
                mma16816(d[mi][2], a[0], a[1], a[2], a[3], bf[4], bf[5]);
                mma16816(d[mi][3], a[0], a[1], a[2], a[3], bf[6], bf[7]);
            }
        }

        if (kc < 3) {
            sts_B((kc + 1) & 1);
            asm volatile("cp.async.wait_group 0;" ::: "memory");
            __syncthreads();
        }
    }

    // ---- epilogue: registers -> gmem ----
    const size_t cbase = (size_t)chunk * NCHUNK;
    const int mbase = mhalf * MTILE;
#pragma unroll
    for (int mi = 0; mi < 4; mi++) {
        const int r0 = mbase + mw + mi * 16 + g;
#pragma unroll
        for (int ni = 0; ni < 4; ni++) {
            const size_t col = cbase + nw + ni * 8 + tg * 2;
            float2 v0 = make_float2(d[mi][ni][0], d[mi][ni][1]);
            float2 v1 = make_float2(d[mi][ni][2], d[mi][ni][3]);
            *reinterpret_cast<float2*>(out + (size_t)r0 * NCOL + col)       = v0;
            *reinterpret_cast<float2*>(out + (size_t)(r0 + 8) * NCOL + col) = v1;
        }
    }
}

// ---------------------------------------------------------------------------
extern "C" void kernel_launch(void* const* d_in, const int* in_sizes, int n_in,
                              void* d_out, int out_size) {
    const float* features = (const float*)d_in[0];
    const float* keys     = (const float*)d_in[1];
    const float* memory   = (const float*)d_in[2];
    float*       out      = (float*)d_out;

    cudaFuncSetAttribute(gemm_kernel,
                         cudaFuncAttributeMaxDynamicSharedMemorySize, DYN_SMEM);

    topk_kernel<<<BATCH / 4, 256>>>(features, keys);
    dim3 grid(NCOL / NCHUNK, BATCH / MTILE);   // 2048 x 2
    gemm_kernel<<<grid, GT, DYN_SMEM>>>(memory, out);
}

// round 8
// speedup vs baseline: 1.3468x; 1.0469x over previous
#include <cuda_runtime.h>
#include <cuda_fp16.h>
#include <cstdint>

#define BATCH   512
#define MEM     256            // K dimension
#define FEAT    512
#define NCOL    131072         // 64*2048
#define TOPK    16

#define NCHUNK  64             // N columns per gemm CTA
#define MTILE   256            // M rows per gemm CTA
#define GT      256            // gemm threads (8 warps)

#define APAD    72             // halfs per A row in smem (64 + 8 pad)
#define BPAD    72             // halfs per B k-row in smem (64 + 8 pad)
#define A_BUF   (MTILE * APAD) // halfs per A k-chunk buffer (18432)
#define B_BUF   (64 * BPAD)    // halfs per B k-chunk buffer (4608)
#define DYN_SMEM ((2 * A_BUF + 2 * B_BUF) * 2)   // 92160 bytes -> 2 CTAs/SM

// Dense fp16 weight matrix W[512][256], linear row-major. Built by kernel 1.
__device__ __align__(16) __half g_W[BATCH * MEM];

// ---------------------------------------------------------------------------
// Kernel 1: cosine sim + top-16 + clamp + renormalize -> dense fp16 W.
// 128 blocks x 256 threads; each block handles 4 batches.  (unchanged)
// ---------------------------------------------------------------------------
__global__ void __launch_bounds__(256)
topk_kernel(const float* __restrict__ features, const float* __restrict__ keys) {
    __shared__ float f_s[4 * FEAT];
    __shared__ float fn_s[4];
    __shared__ float sim_s[4 * 264];
    __shared__ float topv_s[4][TOPK];
    __shared__ int   topi_s[4][TOPK];
    __shared__ float w_dense[4][MEM];

    const int t    = threadIdx.x;
    const int warp = t >> 5;
    const int lane = t & 31;
    const int base = blockIdx.x * 4;

    float4* f4s = reinterpret_cast<float4*>(f_s);
    const float4* fg = reinterpret_cast<const float4*>(features) + (size_t)base * (FEAT / 4);
    for (int i = t; i < 4 * FEAT / 4; i += 256) f4s[i] = fg[i];
    __syncthreads();

    if (warp < 4) {
        float s = 0.f;
#pragma unroll
        for (int m = 0; m < FEAT / 32; m++) {
            float v = f_s[warp * FEAT + lane + m * 32];
            s += v * v;
        }
#pragma unroll
        for (int off = 16; off; off >>= 1) s += __shfl_down_sync(0xffffffffu, s, off);
        if (lane == 0) fn_s[warp] = fmaxf(sqrtf(s), 1e-8f);
    }
    __syncthreads();

    const float4* krow = reinterpret_cast<const float4*>(keys) + (size_t)t * (FEAT / 4);
    float acc[4] = {0.f, 0.f, 0.f, 0.f};
    float kn = 0.f;
#pragma unroll 4
    for (int d = 0; d < FEAT / 4; d++) {
        float4 kv = krow[d];
        kn += kv.x * kv.x + kv.y * kv.y + kv.z * kv.z + kv.w * kv.w;
#pragma unroll
        for (int b = 0; b < 4; b++) {
            float4 fv = f4s[b * (FEAT / 4) + d];
            acc[b] += kv.x * fv.x + kv.y * fv.y + kv.z * fv.z + kv.w * fv.w;
        }
    }
    const float rkn = fmaxf(sqrtf(kn), 1e-8f);
#pragma unroll
    for (int b = 0; b < 4; b++)
        sim_s[b * 264 + t] = acc[b] / (fn_s[b] * rkn);

#pragma unroll
    for (int r = 0; r < 4; r++) w_dense[r][t] = 0.f;
    __syncthreads();

    if (warp < 4) {
        float v[8];
#pragma unroll
        for (int m = 0; m < 8; m++) v[m] = sim_s[warp * 264 + lane * 8 + m];

        for (int k = 0; k < TOPK; k++) {
            float best = v[0];
            int bm = 0;
#pragma unroll
            for (int m = 1; m < 8; m++)
                if (v[m] > best) { best = v[m]; bm = m; }
            int gi = lane * 8 + bm;
#pragma unroll
            for (int off = 16; off; off >>= 1) {
                float ov = __shfl_down_sync(0xffffffffu, best, off);
                int   oi = __shfl_down_sync(0xffffffffu, gi,   off);
                if (ov > best || (ov == best && oi < gi)) { best = ov; gi = oi; }
            }
            best = __shfl_sync(0xffffffffu, best, 0);
            gi   = __shfl_sync(0xffffffffu, gi,   0);
            if (lane == (gi >> 3)) {
                int li = gi & 7;
#pragma unroll
                for (int m = 0; m < 8; m++)
                    if (m == li) v[m] = -3.0e38f;
            }
            if (lane == 0) { topv_s[warp][k] = best; topi_s[warp][k] = gi; }
        }
        __syncwarp();

        float tv = (lane < TOPK) ? fmaxf(topv_s[warp][lane], 0.f) : 0.f;
        float s = tv;
#pragma unroll
        for (int off = 16; off; off >>= 1) s += __shfl_down_sync(0xffffffffu, s, off);
        s = __shfl_sync(0xffffffffu, s, 0);
        const float inv = 1.0f / s;
        if (lane < TOPK)
            w_dense[warp][topi_s[warp][lane]] = tv * inv;
    }
    __syncthreads();

#pragma unroll
    for (int r = 0; r < 4; r++)
        g_W[(base + r) * MEM + t] = __float2half_rn(w_dense[r][t]);
}

// ---------------------------------------------------------------------------
// Kernel 2: HMMA GEMM, 2 CTAs/SM.
// blockIdx.x = mhalf (0/1), blockIdx.y = chunk -> the two CTAs sharing a
// memory chunk are launch-adjacent and co-resident => second B read hits L2.
// Output stores use .cs streaming hint to protect the L2 reuse window.
// ---------------------------------------------------------------------------
__device__ __forceinline__ void mma16816(float d[4],
                                         uint32_t a0, uint32_t a1, uint32_t a2, uint32_t a3,
                                         uint32_t b0, uint32_t b1) {
    asm volatile(
        "mma.sync.aligned.m16n8k16.row.col.f32.f16.f16.f32 "
        "{%0,%1,%2,%3}, {%4,%5,%6,%7}, {%8,%9}, {%0,%1,%2,%3};"
        : "+f"(d[0]), "+f"(d[1]), "+f"(d[2]), "+f"(d[3])
        : "r"(a0), "r"(a1), "r"(a2), "r"(a3), "r"(b0), "r"(b1));
}
__device__ __forceinline__ void ldsm_x4(uint32_t r[4], uint32_t sa) {
    asm volatile("ldmatrix.sync.aligned.m8n8.x4.shared.b16 {%0,%1,%2,%3}, [%4];"
        : "=r"(r[0]), "=r"(r[1]), "=r"(r[2]), "=r"(r[3]) : "r"(sa));
}
__device__ __forceinline__ void ldsm_x4_t(uint32_t r[4], uint32_t sa) {
    asm volatile("ldmatrix.sync.aligned.m8n8.x4.trans.shared.b16 {%0,%1,%2,%3}, [%4];"
        : "=r"(r[0]), "=r"(r[1]), "=r"(r[2]), "=r"(r[3]) : "r"(sa));
}
__device__ __forceinline__ void stg_cs_v2(float* p, float2 v) {
    asm volatile("st.global.cs.v2.f32 [%0], {%1, %2};" :: "l"(p), "f"(v.x), "f"(v.y) : "memory");
}

__global__ void __launch_bounds__(GT, 2)
gemm_kernel(const float* __restrict__ memory, float* __restrict__ out) {
    extern __shared__ __half sm[];
    __half* As = sm;                    // [2][256][APAD]
    __half* Bs = sm + 2 * A_BUF;        // [2][64][BPAD]

    const int tid   = threadIdx.x;
    const int warp  = tid >> 5;
    const int lane  = tid & 31;
    const int g     = lane >> 2;
    const int tg    = lane & 3;
    const int mhalf = blockIdx.x;       // paired dimension (fast-varying)
    const int chunk = blockIdx.y;

    const int mw = (warp >> 1) * 64;    // warp M base within 256
    const int nw = (warp & 1) * 32;     // warp N base

    const uint32_t a_lane = (uint32_t)((mw + (lane & 15)) * APAD + ((lane >> 4) << 3));
    const int bgrp = lane >> 3;
    const uint32_t b_lane = (uint32_t)(((bgrp & 1) * 8 + (lane & 7)) * BPAD
                                       + nw + (bgrp >> 1) * 8);

    const uint32_t As_base = (uint32_t)__cvta_generic_to_shared(As);
    const uint32_t Bs_base = (uint32_t)__cvta_generic_to_shared(Bs);

    // ---- B LDG: 64k x 64n fp32 = 1024 float4; 4 per thread ----
    const float4* msrc = reinterpret_cast<const float4*>(memory) + chunk * (NCHUNK / 4);
    float4 br[4];
    auto ldg_B = [&](int kc) {
#pragma unroll
        for (int q = 0; q < 4; q++) {
            int i = tid + q * GT;
            br[q] = __ldg(&msrc[(size_t)(kc * 64 + (i >> 4)) * (NCOL / 4) + (i & 15)]);
        }
    };
    auto sts_B = [&](int buf) {
#pragma unroll
        for (int q = 0; q < 4; q++) {
            int i = tid + q * GT;
            __half2 h0 = __floats2half2_rn(br[q].x, br[q].y);
            __half2 h1 = __floats2half2_rn(br[q].z, br[q].w);
            uint2* dp = reinterpret_cast<uint2*>(Bs + buf * B_BUF + (i >> 4) * BPAD + (i & 15) * 4);
            *dp = make_uint2(*reinterpret_cast<uint32_t*>(&h0),
                             *reinterpret_cast<uint32_t*>(&h1));
        }
    };
    // ---- A stage: 256 rows x 64 halfs via cp.async 16B granules ----
    auto stage_A = [&](int kc, int buf) {
        const __half* src = g_W + (size_t)(mhalf * MTILE) * MEM + kc * 64;
        __half* dst = As + buf * A_BUF;
#pragma unroll
        for (int j = 0; j < 8; j++) {
            int i = tid + j * GT;                 // 2048 granules total
            int m = i >> 3, seg = i & 7;
            uint32_t sa = (uint32_t)__cvta_generic_to_shared(dst + m * APAD + seg * 8);
            const __half* gp = src + m * MEM + seg * 8;
            asm volatile("cp.async.cg.shared.global [%0], [%1], 16;" :: "r"(sa), "l"(gp) : "memory");
        }
        asm volatile("cp.async.commit_group;" ::: "memory");
    };

    // ---- prologue ----
    ldg_B(0);
    stage_A(0, 0);
    sts_B(0);
    asm volatile("cp.async.wait_group 0;" ::: "memory");
    __syncthreads();

    float d[4][4][4];
#pragma unroll
    for (int mi = 0; mi < 4; mi++)
#pragma unroll
        for (int ni = 0; ni < 4; ni++)
#pragma unroll
            for (int r = 0; r < 4; r++) d[mi][ni][r] = 0.f;

    // ---- K loop: 4 chunks of 64, double-buffered ----
#pragma unroll
    for (int kc = 0; kc < 4; kc++) {
        if (kc < 3) {
            ldg_B(kc + 1);                 // latency hides under mma
            stage_A(kc + 1, (kc + 1) & 1);
        }
        const uint32_t a_base = As_base + ((kc & 1) * A_BUF + a_lane) * 2;
        const uint32_t b_base = Bs_base + ((kc & 1) * B_BUF + b_lane) * 2;

#pragma unroll
        for (int ks = 0; ks < 4; ks++) {
            uint32_t bf[8];
            ldsm_x4_t(bf,     b_base + ks * (16 * BPAD * 2));        // ni 0,1
            ldsm_x4_t(bf + 4, b_base + ks * (16 * BPAD * 2) + 32);   // ni 2,3
#pragma unroll
            for (int mi = 0; mi < 4; mi++) {
                uint32_t a[4];
                ldsm_x4(a, a_base + mi * (16 * APAD * 2) + ks * 32);
                mma16816(d[mi][0], a[0], a[1], a[2], a[3], bf[0], bf[1]);
                mma16816(d[mi][1], a[0], a[1], a[2], a[3], bf[2], bf[3]);
                mma16816(d[mi][2], a[0], a[1], a[2], a[3], bf[4], bf[5]);
                mma16816(d[mi][3], a[0], a[1], a[2], a[3], bf[6], bf[7]);
            }
        }

        if (kc < 3) {
            sts_B((kc + 1) & 1);
            asm volatile("cp.async.wait_group 0;" ::: "memory");
            __syncthreads();
        }
    }

    // ---- epilogue: registers -> gmem, streaming stores ----
    const size_t cbase = (size_t)chunk * NCHUNK;
    const int mbase = mhalf * MTILE;
#pragma unroll
    for (int mi = 0; mi < 4; mi++) {
        const int r0 = mbase + mw + mi * 16 + g;
#pragma unroll
        for (int ni = 0; ni < 4; ni++) {
            const size_t col = cbase + nw + ni * 8 + tg * 2;
            stg_cs_v2(out + (size_t)r0 * NCOL + col,
                      make_float2(d[mi][ni][0], d[mi][ni][1]));
            stg_cs_v2(out + (size_t)(r0 + 8) * NCOL + col,
                      make_float2(d[mi][ni][2], d[mi][ni][3]));
        }
    }
}

// ---------------------------------------------------------------------------
extern "C" void kernel_launch(void* const* d_in, const int* in_sizes, int n_in,
                              void* d_out, int out_size) {
    const float* features = (const float*)d_in[0];
    const float* keys     = (const float*)d_in[1];
    const float* memory   = (const float*)d_in[2];
    float*       out      = (float*)d_out;

    cudaFuncSetAttribute(gemm_kernel,
                         cudaFuncAttributeMaxDynamicSharedMemorySize, DYN_SMEM);

    topk_kernel<<<BATCH / 4, 256>>>(features, keys);
    dim3 grid(BATCH / MTILE, NCOL / NCHUNK);   // (mhalf, chunk) = (2, 2048)
    gemm_kernel<<<grid, GT, DYN_SMEM>>>(memory, out);
}